// round 7
// baseline (speedup 1.0000x reference)
#include <cuda_runtime.h>
#include <cuda_bf16.h>
#include <cstdint>

constexpr int Bb = 64;
constexpr int Ll = 1024;
constexpr int Hh = 512;
constexpr int Tt = 100;
constexpr int Cc = 97;

// Scratch (device globals; no allocations allowed)
__device__ float g_scores[(size_t)Bb * Tt * Ll];    // [B, T, L]
__device__ float g_context[(size_t)Bb * Tt * Hh];   // [B, T, H]

__device__ __forceinline__ uint32_t smem_u32(const void* p) {
    uint32_t a;
    asm("{ .reg .u64 t; cvta.to.shared.u64 t, %1; cvt.u32.u64 %0, t; }"
        : "=r"(a) : "l"(p));
    return a;
}

// hi = top-16-bits-truncated bf16 of x; pack two his with one PRMT
__device__ __forceinline__ uint32_t hi_pack(float x0, float x1) {
    return __byte_perm(__float_as_uint(x0), __float_as_uint(x1), 0x7632);
}
__device__ __forceinline__ float trunc_hi(float x) {
    return __uint_as_float(__float_as_uint(x) & 0xffff0000u);
}
__device__ __forceinline__ uint32_t lo_pack(float l0, float l1) {
    uint32_t r;
    asm("cvt.rn.bf16x2.f32 %0, %1, %2;" : "=r"(r) : "f"(l1), "f"(l0));
    return r;
}
__device__ __forceinline__ void cvt4(float4 x, uint2& h, uint2& l) {
    h.x = hi_pack(x.x, x.y);
    h.y = hi_pack(x.z, x.w);
    l.x = lo_pack(x.x - trunc_hi(x.x), x.y - trunc_hi(x.y));
    l.y = lo_pack(x.z - trunc_hi(x.z), x.w - trunc_hi(x.w));
}

__device__ __forceinline__ void ldmx4(uint32_t* r, uint32_t addr) {
    asm volatile("ldmatrix.sync.aligned.m8n8.x4.shared.b16 {%0,%1,%2,%3}, [%4];"
                 : "=r"(r[0]), "=r"(r[1]), "=r"(r[2]), "=r"(r[3]) : "r"(addr));
}
__device__ __forceinline__ void ldmx4t(uint32_t* r, uint32_t addr) {
    asm volatile("ldmatrix.sync.aligned.m8n8.x4.trans.shared.b16 {%0,%1,%2,%3}, [%4];"
                 : "=r"(r[0]), "=r"(r[1]), "=r"(r[2]), "=r"(r[3]) : "r"(addr));
}

__device__ __forceinline__ void mma16816(float* c, const uint32_t* a,
                                         uint32_t b0, uint32_t b1) {
    asm volatile(
        "mma.sync.aligned.m16n8k16.row.col.f32.bf16.bf16.f32 "
        "{%0,%1,%2,%3}, {%4,%5,%6,%7}, {%8,%9}, {%0,%1,%2,%3};"
        : "+f"(c[0]), "+f"(c[1]), "+f"(c[2]), "+f"(c[3])
        : "r"(a[0]), "r"(a[1]), "r"(a[2]), "r"(a[3]), "r"(b0), "r"(b1));
}

// ---------------------------------------------------------------------------
// HMMA GEMM, fp32 in/out via bf16 3-split, software-pipelined.
//   BMODE 0: B is [n, k] K-major (ldb = row stride); rows >= N_real read 0.
//   BMODE 1: B is [k, n] row-major (ldb = row stride); full tile assumed (K3).
// CTA tile 128x128, 512 threads (16 warps, 2m x 8n, warp tile 64x16), K chunk 32.
// ---------------------------------------------------------------------------
template <int BMODE, bool HAS_BIAS>
__global__ __launch_bounds__(512, 1)
void hmma_gemm(const float* __restrict__ A, const float* __restrict__ Bg,
               float* __restrict__ C, const float* __restrict__ bias,
               int M_real, int N_real, int K,
               int lda, int ldb, int ldc,
               long long sA, long long sB, long long sC)
{
    extern __shared__ char smem[];
    constexpr int ROWB  = 80;                         // A row stride (64B + 16 pad)
    constexpr int ATILE = 128 * ROWB;                 // 10240
    constexpr int BTILE = (BMODE == 0) ? 128 * 80 : 32 * 272;
    constexpr int BUFSZ = 2 * ATILE + 2 * BTILE;      // [A_HI][A_LO][B_HI][B_LO]

    const uint32_t sb = smem_u32(smem);

    const int b = blockIdx.z;
    A  += (long long)b * sA;
    Bg += (long long)b * sB;
    C  += (long long)b * sC;

    const int m0 = blockIdx.y * 128;
    const int n0 = blockIdx.x * 128;
    const int tid = threadIdx.x;
    const int lane = tid & 31;
    const int wid = tid >> 5;
    const int wm = wid & 1;        // 2 warp-rows of 64
    const int wn = wid >> 1;       // 8 warp-cols of 16
    const int gid = lane >> 2;
    const int tig = lane & 3;

    const uint32_t offA = (uint32_t)((wm * 64 + (lane & 15)) * ROWB + (lane >> 4) * 16);
    const uint32_t offB0 = (uint32_t)((wn * 16 + (lane & 7) + ((lane >> 4) & 1) * 8) * 80
                                      + ((lane >> 3) & 1) * 16);
    const uint32_t offB1 = (uint32_t)(((lane & 7) + 8 * ((lane >> 3) & 1)) * 272
                                      + (wn * 16 + ((lane >> 4) & 1) * 8) * 2);

    float acc[4][2][4];
#pragma unroll
    for (int i = 0; i < 4; i++)
#pragma unroll
        for (int j = 0; j < 2; j++)
#pragma unroll
            for (int k = 0; k < 4; k++) acc[i][j][k] = 0.0f;

    float4 ar[2], br[2];

    auto loadA = [&](int kc) {
#pragma unroll
        for (int i = 0; i < 2; ++i) {
            int v = i * 512 + tid;
            int row = v >> 3, q = v & 7;
            int m = m0 + row;
            ar[i] = make_float4(0.f, 0.f, 0.f, 0.f);
            if (m < M_real)
                ar[i] = *(const float4*)(A + (long long)m * lda + kc + q * 4);
        }
    };
    auto loadB = [&](int kc) {
        if (BMODE == 0) {
#pragma unroll
            for (int i = 0; i < 2; ++i) {
                int v = i * 512 + tid;
                int row = v >> 3, q = v & 7;
                int n = n0 + row;
                br[i] = make_float4(0.f, 0.f, 0.f, 0.f);
                if (n < N_real)
                    br[i] = *(const float4*)(Bg + (long long)n * ldb + kc + q * 4);
            }
        } else {
#pragma unroll
            for (int i = 0; i < 2; ++i) {
                int v = i * 512 + tid;
                int r = v >> 5, c4 = v & 31;
                br[i] = *(const float4*)(Bg + (long long)(kc + r) * ldb + n0 + c4 * 4);
            }
        }
    };
    auto storeTiles = [&](int buf) {
        char* base = smem + buf * BUFSZ;
#pragma unroll
        for (int i = 0; i < 2; ++i) {
            int v = i * 512 + tid;
            int row = v >> 3, q = v & 7;
            uint2 h, l;
            cvt4(ar[i], h, l);
            *(uint2*)(base + row * ROWB + q * 8) = h;
            *(uint2*)(base + ATILE + row * ROWB + q * 8) = l;
        }
        if (BMODE == 0) {
#pragma unroll
            for (int i = 0; i < 2; ++i) {
                int v = i * 512 + tid;
                int row = v >> 3, q = v & 7;
                uint2 h, l;
                cvt4(br[i], h, l);
                *(uint2*)(base + 2 * ATILE + row * 80 + q * 8) = h;
                *(uint2*)(base + 2 * ATILE + BTILE + row * 80 + q * 8) = l;
            }
        } else {
#pragma unroll
            for (int i = 0; i < 2; ++i) {
                int v = i * 512 + tid;
                int r = v >> 5, c4 = v & 31;
                uint2 h, l;
                cvt4(br[i], h, l);
                *(uint2*)(base + 2 * ATILE + r * 272 + c4 * 8) = h;
                *(uint2*)(base + 2 * ATILE + BTILE + r * 272 + c4 * 8) = l;
            }
        }
    };

    const int nchunks = K >> 5;
    loadA(0);
    loadB(0);

#pragma unroll 1
    for (int c = 0; c < nchunks; ++c) {
        const int buf = c & 1;
        storeTiles(buf);
        __syncthreads();

        if (c + 1 < nchunks) {
            loadA((c + 1) << 5);
            loadB((c + 1) << 5);
        }

        const uint32_t tbase = sb + buf * BUFSZ;
        const uint32_t pAhi = tbase + offA;
        const uint32_t pAlo = pAhi + ATILE;

#pragma unroll
        for (int ks = 0; ks < 2; ++ks) {
            uint32_t ahi[4][4], alo[4][4];
#pragma unroll
            for (int mi = 0; mi < 4; ++mi) {
                ldmx4(ahi[mi], pAhi + mi * (16 * ROWB) + ks * 32);
                ldmx4(alo[mi], pAlo + mi * (16 * ROWB) + ks * 32);
            }
            uint32_t bh[2][2], bl[2][2];
            if (BMODE == 0) {
                const uint32_t pBhi = tbase + 2 * ATILE + offB0;
                const uint32_t pBlo = pBhi + BTILE;
                uint32_t t[4];
                ldmx4(t, pBhi + ks * 32);
                bh[0][0] = t[0]; bh[0][1] = t[1]; bh[1][0] = t[2]; bh[1][1] = t[3];
                ldmx4(t, pBlo + ks * 32);
                bl[0][0] = t[0]; bl[0][1] = t[1]; bl[1][0] = t[2]; bl[1][1] = t[3];
            } else {
                const uint32_t pBhi = tbase + 2 * ATILE + offB1 + ks * (16 * 272);
                const uint32_t pBlo = pBhi + BTILE;
                uint32_t t[4];
                ldmx4t(t, pBhi);
                bh[0][0] = t[0]; bh[0][1] = t[1]; bh[1][0] = t[2]; bh[1][1] = t[3];
                ldmx4t(t, pBlo);
                bl[0][0] = t[0]; bl[0][1] = t[1]; bl[1][0] = t[2]; bl[1][1] = t[3];
            }
#pragma unroll
            for (int mi = 0; mi < 4; ++mi) {
#pragma unroll
                for (int nt = 0; nt < 2; ++nt) {
                    mma16816(acc[mi][nt], ahi[mi], bh[nt][0], bh[nt][1]);
                    mma16816(acc[mi][nt], ahi[mi], bl[nt][0], bl[nt][1]);
                    mma16816(acc[mi][nt], alo[mi], bh[nt][0], bh[nt][1]);
                }
            }
        }
        // single barrier per chunk: next convert targets the other buffer;
        // passing this barrier implies mma(c-1) (last reader) finished.
    }

    // ---- Epilogue
#pragma unroll
    for (int mi = 0; mi < 4; ++mi) {
#pragma unroll
        for (int nt = 0; nt < 2; ++nt) {
            int r0 = m0 + wm * 64 + mi * 16 + gid;
            int cb = n0 + wn * 16 + nt * 8 + tig * 2;
#pragma unroll
            for (int half = 0; half < 2; ++half) {
                int r = r0 + half * 8;
                if (r < M_real) {
                    float v0 = acc[mi][nt][half * 2 + 0];
                    float v1 = acc[mi][nt][half * 2 + 1];
                    if (cb < N_real) {
                        float o = v0;
                        if (HAS_BIAS) o += bias[cb];
                        C[(long long)r * ldc + cb] = o;
                    }
                    if (cb + 1 < N_real) {
                        float o = v1;
                        if (HAS_BIAS) o += bias[cb + 1];
                        C[(long long)r * ldc + cb + 1] = o;
                    }
                }
            }
        }
    }
}

// ---------------------------------------------------------------------------
// Softmax over 1024 contiguous elements per row; one block per row.
// ---------------------------------------------------------------------------
__global__ __launch_bounds__(256)
void softmax1024(float* __restrict__ data)
{
    const long long row = blockIdx.x;
    float* p = data + row * 1024;
    const int tid = threadIdx.x;

    float4 v = ((const float4*)p)[tid];
    float mx = fmaxf(fmaxf(v.x, v.y), fmaxf(v.z, v.w));
#pragma unroll
    for (int o = 16; o > 0; o >>= 1)
        mx = fmaxf(mx, __shfl_xor_sync(0xffffffffu, mx, o));

    __shared__ float red[8];
    if ((tid & 31) == 0) red[tid >> 5] = mx;
    __syncthreads();
    float mall = red[0];
#pragma unroll
    for (int i = 1; i < 8; i++) mall = fmaxf(mall, red[i]);
    __syncthreads();

    float4 e;
    e.x = __expf(v.x - mall); e.y = __expf(v.y - mall);
    e.z = __expf(v.z - mall); e.w = __expf(v.w - mall);

    float s = e.x + e.y + e.z + e.w;
#pragma unroll
    for (int o = 16; o > 0; o >>= 1)
        s += __shfl_xor_sync(0xffffffffu, s, o);
    if ((tid & 31) == 0) red[tid >> 5] = s;
    __syncthreads();
    float sall = 0.0f;
#pragma unroll
    for (int i = 0; i < 8; i++) sall += red[i];

    float inv = 1.0f / sall;
    e.x *= inv; e.y *= inv; e.z *= inv; e.w *= inv;
    ((float4*)p)[tid] = e;
}

// ---------------------------------------------------------------------------
extern "C" void kernel_launch(void* const* d_in, const int* in_sizes, int n_in,
                              void* d_out, int out_size)
{
    const float* pf   = (const float*)d_in[0];  // position_fmap [B, L, H]
    const float* of   = (const float*)d_in[1];  // origin_fmap   [B, L, H]
    const float* emb  = (const float*)d_in[2];  // pos_emb       [T, H]
    const float* W    = (const float*)d_in[3];  // W_gen         [C, H]
    const float* bias = (const float*)d_in[4];  // b_gen         [C]
    float* out = (float*)d_out;                 // [B, T, C]

    float* scores = nullptr;
    float* context = nullptr;
    cudaGetSymbolAddress((void**)&scores, g_scores);
    cudaGetSymbolAddress((void**)&context, g_context);

    constexpr int SMEM0 = 2 * (2 * 128 * 80 + 2 * 128 * 80);   // 81920
    constexpr int SMEM1 = 2 * (2 * 128 * 80 + 2 * 32 * 272);   // 75776
    cudaFuncSetAttribute((const void*)hmma_gemm<0, false>,
                         cudaFuncAttributeMaxDynamicSharedMemorySize, SMEM0);
    cudaFuncSetAttribute((const void*)hmma_gemm<1, false>,
                         cudaFuncAttributeMaxDynamicSharedMemorySize, SMEM1);
    cudaFuncSetAttribute((const void*)hmma_gemm<0, true>,
                         cudaFuncAttributeMaxDynamicSharedMemorySize, SMEM0);

    // K1: scores[b, t, l] = sum_h emb[t, h] * pf[b, l, h]
    {
        dim3 grid(Ll / 128, 1, Bb);
        hmma_gemm<0, false><<<grid, 512, SMEM0>>>(
            emb, pf, scores, nullptr,
            Tt, Ll, Hh,
            Hh, Hh, Ll,
            0LL, (long long)Ll * Hh, (long long)Tt * Ll);
    }

    // K2: softmax over L per (b, t) row
    softmax1024<<<Bb * Tt, 256>>>(scores);

    // K3: context[b, t, h] = sum_l attn[b, t, l] * of[b, l, h]
    //     B = of[b] is [k=l, n=h] row-major -> BMODE 1 (ldmatrix.trans)
    {
        dim3 grid(Hh / 128, 1, Bb);
        hmma_gemm<1, false><<<grid, 512, SMEM1>>>(
            scores, of, context, nullptr,
            Tt, Hh, Ll,
            Ll, Hh, Hh,
            (long long)Tt * Ll, (long long)Ll * Hh, (long long)Tt * Hh);
    }

    // K4: out[bt, c] = sum_h context[bt, h] * W[c, h] + bias[c]
    {
        dim3 grid(1, (Bb * Tt) / 128, 1);
        hmma_gemm<0, true><<<grid, 512, SMEM0>>>(
            context, W, out, bias,
            Bb * Tt, Cc, Hh,
            Hh, Hh, Cc,
            0LL, 0LL, 0LL);
    }
}